// round 2
// baseline (speedup 1.0000x reference)
#include <cuda_runtime.h>

#define NN 100000
#define EE 1600000
#define GG 512
#define XD 79
#define HH 64

// ---------------- scratch (static __device__, no allocations) ----------------
__device__ float d_h[NN * HH];
__device__ float d_m[NN * HH];
__device__ float d_agg[NN * HH];
__device__ float d_gi[NN * 192];
__device__ int   d_deg[NN];
__device__ int   d_rowptr[NN + 1];
__device__ int   d_cursor[NN];
__device__ int   d_col[EE];
__device__ float d_pooled[GG * HH];
__device__ float d_cnt[GG];

// ---------------- f32x2 packed helpers (Blackwell FFMA2) ----------------
typedef unsigned long long u64;

__device__ __forceinline__ u64 fma2(u64 a, u64 b, u64 c) {
    u64 d; asm("fma.rn.f32x2 %0,%1,%2,%3;" : "=l"(d) : "l"(a), "l"(b), "l"(c)); return d;
}
__device__ __forceinline__ u64 add2(u64 a, u64 b) {
    u64 d; asm("add.rn.f32x2 %0,%1,%2;" : "=l"(d) : "l"(a), "l"(b)); return d;
}
__device__ __forceinline__ u64 pk2(float x, float y) {
    u64 r; asm("mov.b64 %0,{%1,%2};" : "=l"(r) : "f"(x), "f"(y)); return r;
}
__device__ __forceinline__ u64 b2(float x) { return pk2(x, x); }
__device__ __forceinline__ float2 up2(u64 v) {
    float2 r; asm("mov.b64 {%0,%1},%2;" : "=f"(r.x), "=f"(r.y) : "l"(v)); return r;
}
__device__ __forceinline__ float sigf(float x) { return 1.0f / (1.0f + __expf(-x)); }

// ---------------- init / CSR build ----------------
__global__ void k_zero() {
    int t = blockIdx.x * blockDim.x + threadIdx.x;
    if (t < NN) d_deg[t] = 0;
    if (t < GG * HH) d_pooled[t] = 0.0f;
    if (t < GG) d_cnt[t] = 0.0f;
}

__global__ void k_count(const int* __restrict__ ei) {
    int e = blockIdx.x * blockDim.x + threadIdx.x;
    if (e < EE) atomicAdd(&d_deg[ei[EE + e]], 1);
}

__global__ void k_scan() {  // single block, 1024 threads: exclusive scan of deg -> rowptr/cursor
    __shared__ int wsum[32];
    __shared__ int carry;
    int t = threadIdx.x, lane = t & 31, wid = t >> 5;
    if (t == 0) carry = 0;
    __syncthreads();
    for (int base = 0; base < NN; base += 1024) {
        int i = base + t;
        int v = (i < NN) ? d_deg[i] : 0;
        int incl = v;
        #pragma unroll
        for (int o = 1; o < 32; o <<= 1) {
            int u = __shfl_up_sync(0xffffffffu, incl, o);
            if (lane >= o) incl += u;
        }
        if (lane == 31) wsum[wid] = incl;
        __syncthreads();
        if (wid == 0) {
            int si = wsum[lane];
            #pragma unroll
            for (int o = 1; o < 32; o <<= 1) {
                int u = __shfl_up_sync(0xffffffffu, si, o);
                if (lane >= o) si += u;
            }
            wsum[lane] = si;
        }
        __syncthreads();
        int off = (wid ? wsum[wid - 1] : 0) + carry;
        int total = wsum[31];
        if (i < NN) {
            d_rowptr[i + 1] = off + incl;
            d_cursor[i] = off + incl - v;
        }
        __syncthreads();
        if (t == 0) carry += total;
        __syncthreads();
    }
    if (t == 0) d_rowptr[0] = 0;
}

__global__ void k_fill(const int* __restrict__ ei) {
    int e = blockIdx.x * blockDim.x + threadIdx.x;
    if (e < EE) {
        int dst = ei[EE + e];
        int p = atomicAdd(&d_cursor[dst], 1);
        d_col[p] = ei[e];
    }
}

// ---------------- input projection: h = x @ Wp^T + bp ----------------
__global__ void k_proj(const float* __restrict__ x, const float* __restrict__ Wp,
                       const float* __restrict__ bp) {
    __shared__ float2 sw[XD * 32];  // [k][lane] = (Wp[2L][k], Wp[2L+1][k])
    int t = threadIdx.x;
    for (int e = t; e < XD * 32; e += blockDim.x) {
        int k = e >> 5, L = e & 31;
        sw[e] = make_float2(Wp[(2 * L) * XD + k], Wp[(2 * L + 1) * XD + k]);
    }
    __syncthreads();
    int lane = t & 31;
    int w = blockIdx.x * (blockDim.x >> 5) + (t >> 5);
    int nw = gridDim.x * (blockDim.x >> 5);
    u64 bias = pk2(bp[2 * lane], bp[2 * lane + 1]);
    for (int n = w; n < NN; n += nw) {
        const float* xr = x + n * XD;
        u64 acc = bias;
        #pragma unroll 8
        for (int k = 0; k < XD; k++) {
            float xv = __ldg(&xr[k]);
            u64 wv = *reinterpret_cast<const u64*>(&sw[k * 32 + lane]);
            acc = fma2(wv, b2(xv), acc);
        }
        reinterpret_cast<u64*>(d_h + n * HH)[lane] = acc;
    }
}

// ---------------- m = h @ W  (W row-major [64][64]) ----------------
__global__ void __launch_bounds__(256) k_mm64(const float* __restrict__ W) {
    __shared__ float2 sw[HH * 32];  // direct float2 view of W: [k][pair j]
    int t = threadIdx.x;
    for (int e = t; e < HH * 32; e += blockDim.x) sw[e] = ((const float2*)W)[e];
    __syncthreads();
    int lane = t & 31, wl = t >> 5;
    int w = blockIdx.x * 8 + wl, nw = gridDim.x * 8;
    for (int base = w * 4; base < NN; base += nw * 4) {
        float2 hr[4];
        #pragma unroll
        for (int i = 0; i < 4; i++)
            hr[i] = ((const float2*)(d_h + (base + i) * HH))[lane];
        u64 a0 = 0, a1 = 0, a2 = 0, a3 = 0;
        #pragma unroll 16
        for (int k = 0; k < HH; k++) {
            u64 wv = *reinterpret_cast<const u64*>(&sw[k * 32 + lane]);
            int sl = k >> 1;
            float v0 = __shfl_sync(0xffffffffu, (k & 1) ? hr[0].y : hr[0].x, sl);
            float v1 = __shfl_sync(0xffffffffu, (k & 1) ? hr[1].y : hr[1].x, sl);
            float v2 = __shfl_sync(0xffffffffu, (k & 1) ? hr[2].y : hr[2].x, sl);
            float v3 = __shfl_sync(0xffffffffu, (k & 1) ? hr[3].y : hr[3].x, sl);
            a0 = fma2(wv, b2(v0), a0);
            a1 = fma2(wv, b2(v1), a1);
            a2 = fma2(wv, b2(v2), a2);
            a3 = fma2(wv, b2(v3), a3);
        }
        reinterpret_cast<u64*>(d_m + (base + 0) * HH)[lane] = a0;
        reinterpret_cast<u64*>(d_m + (base + 1) * HH)[lane] = a1;
        reinterpret_cast<u64*>(d_m + (base + 2) * HH)[lane] = a2;
        reinterpret_cast<u64*>(d_m + (base + 3) * HH)[lane] = a3;
    }
}

// ---------------- agg[d] = sum over in-edges of m[src]  (CSR, no atomics) ----------------
__global__ void k_aggregate() {
    int lane = threadIdx.x & 31;
    int w = blockIdx.x * (blockDim.x >> 5) + (threadIdx.x >> 5);
    if (w >= NN) return;
    int e0 = d_rowptr[w], e1 = d_rowptr[w + 1];
    u64 acc = 0;
    for (int e = e0; e < e1; e++) {
        int s = __ldg(&d_col[e]);
        acc = add2(acc, reinterpret_cast<const u64*>(d_m + s * HH)[lane]);
    }
    reinterpret_cast<u64*>(d_agg + w * HH)[lane] = acc;
}

// ---------------- GRU phase 1: gi = agg @ Wih^T + bih -> d_gi [N,3,64] ----------------
__global__ void __launch_bounds__(256) k_gi(const float* __restrict__ Wih,
                                            const float* __restrict__ bih) {
    __shared__ float2 w[64 * 96];  // [k][gate*32 + lane] = cols (g*64+2L, g*64+2L+1)
    int t = threadIdx.x;
    for (int e = t; e < 64 * 96; e += 256) {
        int k = e / 96, r = e % 96, g = r >> 5, L = r & 31;
        int c = g * 64 + 2 * L;
        w[e] = make_float2(Wih[c * 64 + k], Wih[(c + 1) * 64 + k]);
    }
    __syncthreads();
    int lane = t & 31, wl = t >> 5;
    u64 bi0 = pk2(bih[2 * lane], bih[2 * lane + 1]);
    u64 bi1 = pk2(bih[64 + 2 * lane], bih[64 + 2 * lane + 1]);
    u64 bi2 = pk2(bih[128 + 2 * lane], bih[128 + 2 * lane + 1]);
    int wp = blockIdx.x * 8 + wl, nw = gridDim.x * 8;
    for (int base = wp * 4; base < NN; base += nw * 4) {
        float2 a[4];
        #pragma unroll
        for (int i = 0; i < 4; i++)
            a[i] = ((const float2*)(d_agg + (base + i) * HH))[lane];
        u64 acc[4][3];
        #pragma unroll
        for (int i = 0; i < 4; i++) { acc[i][0] = bi0; acc[i][1] = bi1; acc[i][2] = bi2; }
        #pragma unroll 16
        for (int k = 0; k < 64; k++) {
            const u64* wr = reinterpret_cast<const u64*>(w + k * 96) + lane;
            u64 w0 = wr[0], w1 = wr[32], w2 = wr[64];
            int sl = k >> 1;
            #pragma unroll
            for (int i = 0; i < 4; i++) {
                float v = __shfl_sync(0xffffffffu, (k & 1) ? a[i].y : a[i].x, sl);
                u64 vb = b2(v);
                acc[i][0] = fma2(w0, vb, acc[i][0]);
                acc[i][1] = fma2(w1, vb, acc[i][1]);
                acc[i][2] = fma2(w2, vb, acc[i][2]);
            }
        }
        #pragma unroll
        for (int i = 0; i < 4; i++) {
            u64* o = reinterpret_cast<u64*>(d_gi + (base + i) * 192);
            o[lane] = acc[i][0];
            o[32 + lane] = acc[i][1];
            o[64 + lane] = acc[i][2];
        }
    }
}

// ---------------- GRU phase 2: gh = h @ Whh^T + bhh, gates, h update ----------------
__global__ void __launch_bounds__(256) k_gh(const float* __restrict__ Whh,
                                            const float* __restrict__ bhh,
                                            int dorelu) {
    __shared__ float2 w[64 * 96];
    int t = threadIdx.x;
    for (int e = t; e < 64 * 96; e += 256) {
        int k = e / 96, r = e % 96, g = r >> 5, L = r & 31;
        int c = g * 64 + 2 * L;
        w[e] = make_float2(Whh[c * 64 + k], Whh[(c + 1) * 64 + k]);
    }
    __syncthreads();
    int lane = t & 31, wl = t >> 5;
    u64 bh0 = pk2(bhh[2 * lane], bhh[2 * lane + 1]);
    u64 bh1 = pk2(bhh[64 + 2 * lane], bhh[64 + 2 * lane + 1]);
    u64 bh2 = pk2(bhh[128 + 2 * lane], bhh[128 + 2 * lane + 1]);
    int wp = blockIdx.x * 8 + wl, nw = gridDim.x * 8;
    for (int base = wp * 4; base < NN; base += nw * 4) {
        float2 hv[4];
        #pragma unroll
        for (int i = 0; i < 4; i++)
            hv[i] = ((const float2*)(d_h + (base + i) * HH))[lane];
        u64 acc[4][3];
        #pragma unroll
        for (int i = 0; i < 4; i++) { acc[i][0] = bh0; acc[i][1] = bh1; acc[i][2] = bh2; }
        #pragma unroll 16
        for (int k = 0; k < 64; k++) {
            const u64* wr = reinterpret_cast<const u64*>(w + k * 96) + lane;
            u64 w0 = wr[0], w1 = wr[32], w2 = wr[64];
            int sl = k >> 1;
            #pragma unroll
            for (int i = 0; i < 4; i++) {
                float v = __shfl_sync(0xffffffffu, (k & 1) ? hv[i].y : hv[i].x, sl);
                u64 vb = b2(v);
                acc[i][0] = fma2(w0, vb, acc[i][0]);
                acc[i][1] = fma2(w1, vb, acc[i][1]);
                acc[i][2] = fma2(w2, vb, acc[i][2]);
            }
        }
        #pragma unroll
        for (int i = 0; i < 4; i++) {
            const u64* gp = reinterpret_cast<const u64*>(d_gi + (base + i) * 192);
            float2 i0 = up2(gp[lane]), i1 = up2(gp[32 + lane]), i2 = up2(gp[64 + lane]);
            float2 h0 = up2(acc[i][0]), h1 = up2(acc[i][1]), h2v = up2(acc[i][2]);
            float rx = sigf(i0.x + h0.x), ry = sigf(i0.y + h0.y);
            float zx = sigf(i1.x + h1.x), zy = sigf(i1.y + h1.y);
            float nx = tanhf(i2.x + rx * h2v.x), ny = tanhf(i2.y + ry * h2v.y);
            float ox = (1.0f - zx) * nx + zx * hv[i].x;
            float oy = (1.0f - zy) * ny + zy * hv[i].y;
            if (dorelu) { ox = fmaxf(ox, 0.0f); oy = fmaxf(oy, 0.0f); }
            reinterpret_cast<u64*>(d_h + (base + i) * HH)[lane] = pk2(ox, oy);
        }
    }
}

// ---------------- mean pool by graph ----------------
__global__ void k_pool(const int* __restrict__ batch) {
    int t = blockIdx.x * blockDim.x + threadIdx.x;
    if (t >= NN * 32) return;
    int n = t >> 5, L = t & 31;
    int g = __ldg(&batch[n]);
    float2 hv = ((const float2*)(d_h + n * HH))[L];
    atomicAdd(&d_pooled[g * HH + 2 * L], hv.x);
    atomicAdd(&d_pooled[g * HH + 2 * L + 1], hv.y);
    if (L == 0) atomicAdd(&d_cnt[g], 1.0f);
}

// ---------------- MLP head + sigmoid ----------------
__global__ void k_mlp(const float* __restrict__ W1, const float* __restrict__ b1,
                      const float* __restrict__ W2, const float* __restrict__ b2,
                      const float* __restrict__ W3, const float* __restrict__ b3,
                      float* __restrict__ out) {
    __shared__ float p[64], o1[64], o2[32];
    int g = blockIdx.x, t = threadIdx.x;
    float inv = 1.0f / fmaxf(d_cnt[g], 1.0f);
    p[t] = d_pooled[g * 64 + t] * inv;
    __syncthreads();
    float a = b1[t];
    #pragma unroll 8
    for (int k = 0; k < 64; k++) a += W1[t * 64 + k] * p[k];
    o1[t] = a;
    __syncthreads();
    if (t < 32) {
        float a2 = b2[t];
        #pragma unroll 8
        for (int k = 0; k < 64; k++) a2 += W2[t * 64 + k] * o1[k];
        o2[t] = a2;
    }
    __syncthreads();
    if (t == 0) {
        float z = b3[0];
        #pragma unroll
        for (int k = 0; k < 32; k++) z += W3[k] * o2[k];
        out[g] = 1.0f / (1.0f + __expf(-z));
    }
}

// ---------------- launch ----------------
extern "C" void kernel_launch(void* const* d_in, const int* in_sizes, int n_in,
                              void* d_out, int out_size) {
    const float* x      = (const float*)d_in[0];
    const int*   ei     = (const int*)  d_in[1];
    const int*   batch  = (const int*)  d_in[2];
    const float* Wproj  = (const float*)d_in[3];
    const float* bproj  = (const float*)d_in[4];
    const float* ggcW   = (const float*)d_in[5];
    const float* gWih   = (const float*)d_in[6];
    const float* gWhh   = (const float*)d_in[7];
    const float* gbih   = (const float*)d_in[8];
    const float* gbhh   = (const float*)d_in[9];
    const float* W1     = (const float*)d_in[10];
    const float* b1     = (const float*)d_in[11];
    const float* W2     = (const float*)d_in[12];
    const float* b2     = (const float*)d_in[13];
    const float* W3     = (const float*)d_in[14];
    const float* b3     = (const float*)d_in[15];
    float* out = (float*)d_out;

    k_zero<<<(NN + 255) / 256, 256>>>();
    k_count<<<(EE + 255) / 256, 256>>>(ei);
    k_scan<<<1, 1024>>>();
    k_fill<<<(EE + 255) / 256, 256>>>(ei);
    k_proj<<<592, 256>>>(x, Wproj, bproj);

    for (int b = 0; b < 4; b++) {
        for (int l = 0; l < 2; l++) {
            k_mm64<<<592, 256>>>(ggcW + (b * 2 + l) * HH * HH);
            k_aggregate<<<(NN + 7) / 8, 256>>>();
            k_gi<<<592, 256>>>(gWih + b * 192 * 64, gbih + b * 192);
            k_gh<<<592, 256>>>(gWhh + b * 192 * 64, gbhh + b * 192, l == 1 ? 1 : 0);
        }
    }

    k_pool<<<(NN * 32 + 255) / 256, 256>>>(batch);
    k_mlp<<<GG, 64>>>(W1, b1, W2, b2, W3, b3, out);
}